// round 2
// baseline (speedup 1.0000x reference)
#include <cuda_runtime.h>
#include <cuda_bf16.h>

// Problem constants (guarded by runtime sizes)
#define MAX_NODES 500000
#define MAX_GRAPHS 8192
#define FDIM 16

// Scratch (device globals — no allocation allowed)
__device__ float g_deg[MAX_NODES];              // deg -> dinv in place
__device__ float g_h[MAX_NODES * FDIM];         // h (pre-aggregation features)
__device__ float g_agg[MAX_NODES * FDIM];       // aggregation target
__device__ float g_pool[MAX_GRAPHS * FDIM];
__device__ float g_cnt[MAX_GRAPHS];

// ---------------------------------------------------------------------------
// 1) deg init to 1 (self-loop contribution)
__global__ void k_init_deg(int N) {
    int n = blockIdx.x * blockDim.x + threadIdx.x;
    if (n < N) g_deg[n] = 1.0f;
}

// 2) deg count over edge targets (col = edge_index[1])
__global__ void k_deg_count(const int* __restrict__ cols, int E) {
    int e = blockIdx.x * blockDim.x + threadIdx.x;
    if (e < E) atomicAdd(&g_deg[cols[e]], 1.0f);
}

// 3) dinv = rsqrt(deg) in place (deg >= 1 always)
__global__ void k_dinv(int N) {
    int n = blockIdx.x * blockDim.x + threadIdx.x;
    if (n < N) g_deg[n] = rsqrtf(g_deg[n]);
}

// 4) layer1: h = x @ W1 ; agg = h * dinv^2  (self-loop term)
__global__ void k_layer1(const float* __restrict__ x, const float* __restrict__ W1,
                         int N) {
    int n = blockIdx.x * blockDim.x + threadIdx.x;
    if (n >= N) return;
    float xi[9];
#pragma unroll
    for (int k = 0; k < 9; k++) xi[k] = x[n * 9 + k];
    float di = g_deg[n];
    float di2 = di * di;
#pragma unroll
    for (int f = 0; f < FDIM; f++) {
        float s = 0.0f;
#pragma unroll
        for (int k = 0; k < 9; k++) s += xi[k] * __ldg(&W1[k * FDIM + f]);
        g_h[n * FDIM + f] = s;
        g_agg[n * FDIM + f] = s * di2;
    }
}

// 5) edge scatter: agg[col] += h[row] * dinv[row] * dinv[col]
//    16 threads per edge (one per feature), coalesced gather + atomic scatter.
__global__ void k_scatter(const int* __restrict__ rows,
                          const int* __restrict__ cols, int E) {
    long long idx = (long long)blockIdx.x * blockDim.x + threadIdx.x;
    int e = (int)(idx >> 4);
    int f = (int)(idx & 15);
    if (e >= E) return;
    int r = rows[e];
    int c = cols[e];
    float norm = g_deg[r] * g_deg[c];
    float v = g_h[r * FDIM + f] * norm;
    atomicAdd(&g_agg[c * FDIM + f], v);
}

// 6) finalize layer1 + layer2 matmul: a = relu(agg + b1); h = a @ W2; agg = h*dinv^2
__global__ void k_layer2(const float* __restrict__ b1, const float* __restrict__ W2,
                         int N) {
    int n = blockIdx.x * blockDim.x + threadIdx.x;
    if (n >= N) return;
    float a[FDIM];
#pragma unroll
    for (int f = 0; f < FDIM; f++) {
        float v = g_agg[n * FDIM + f] + __ldg(&b1[f]);
        a[f] = v > 0.0f ? v : 0.0f;
    }
    float di = g_deg[n];
    float di2 = di * di;
#pragma unroll
    for (int f = 0; f < FDIM; f++) {
        float s = 0.0f;
#pragma unroll
        for (int k = 0; k < FDIM; k++) s += a[k] * __ldg(&W2[k * FDIM + f]);
        g_h[n * FDIM + f] = s;
        g_agg[n * FDIM + f] = s * di2;
    }
}

// 7) zero pooling buffers
__global__ void k_zero_pool(int G) {
    int i = blockIdx.x * blockDim.x + threadIdx.x;
    if (i < G * FDIM) g_pool[i] = 0.0f;
    if (i < G) g_cnt[i] = 0.0f;
}

// 8) pool: relu(agg + b2) atomically accumulated per graph
__global__ void k_pool(const int* __restrict__ batch,
                       const float* __restrict__ b2, int N) {
    long long idx = (long long)blockIdx.x * blockDim.x + threadIdx.x;
    int n = (int)(idx >> 4);
    int f = (int)(idx & 15);
    if (n >= N) return;
    int g = batch[n];
    float v = g_agg[n * FDIM + f] + __ldg(&b2[f]);
    v = v > 0.0f ? v : 0.0f;
    atomicAdd(&g_pool[g * FDIM + f], v);
    if (f == 0) atomicAdd(&g_cnt[g], 1.0f);
}

// 9) MLP head: z = relu([emb, meta] @ Wh1 + bh1); out = z @ Wh2 + bh2
__global__ void k_mlp(const float* __restrict__ meta,
                      const float* __restrict__ Wh1, const float* __restrict__ bh1,
                      const float* __restrict__ Wh2, const float* __restrict__ bh2,
                      float* __restrict__ out, int G) {
    int g = blockIdx.x * blockDim.x + threadIdx.x;
    if (g >= G) return;
    float cnt = g_cnt[g];
    float inv = 1.0f / fmaxf(cnt, 1.0f);
    float z[FDIM];
#pragma unroll
    for (int f = 0; f < FDIM; f++) z[f] = __ldg(&bh1[f]);
#pragma unroll
    for (int k = 0; k < FDIM; k++) {
        float e = g_pool[g * FDIM + k] * inv;
#pragma unroll
        for (int f = 0; f < FDIM; f++) z[f] += e * __ldg(&Wh1[k * FDIM + f]);
    }
    for (int k = 0; k < 27; k++) {
        float m = meta[g * 27 + k];
#pragma unroll
        for (int f = 0; f < FDIM; f++) z[f] += m * __ldg(&Wh1[(FDIM + k) * FDIM + f]);
    }
    float o = __ldg(&bh2[0]);
#pragma unroll
    for (int f = 0; f < FDIM; f++) {
        float zz = z[f] > 0.0f ? z[f] : 0.0f;
        o += zz * __ldg(&Wh2[f]);
    }
    out[g] = o;
}

extern "C" void kernel_launch(void* const* d_in, const int* in_sizes, int n_in,
                              void* d_out, int out_size) {
    const float* x    = (const float*)d_in[0];
    const int*   ei   = (const int*)d_in[1];    // int32 (JAX default x64 disabled)
    const int*   batch= (const int*)d_in[2];
    const float* meta = (const float*)d_in[3];
    const float* W1   = (const float*)d_in[4];
    const float* b1   = (const float*)d_in[5];
    const float* W2   = (const float*)d_in[6];
    const float* b2   = (const float*)d_in[7];
    const float* Wh1  = (const float*)d_in[8];
    const float* bh1  = (const float*)d_in[9];
    const float* Wh2  = (const float*)d_in[10];
    const float* bh2  = (const float*)d_in[11];
    float* out = (float*)d_out;

    const int N = in_sizes[0] / 9;
    const int E = in_sizes[1] / 2;
    const int G = in_sizes[3] / 27;

    const int* rows = ei;      // edge_index[0] = source
    const int* cols = ei + E;  // edge_index[1] = target

    const int B = 256;
    k_init_deg<<<(N + B - 1) / B, B>>>(N);
    k_deg_count<<<(E + B - 1) / B, B>>>(cols, E);
    k_dinv<<<(N + B - 1) / B, B>>>(N);
    k_layer1<<<(N + 127) / 128, 128>>>(x, W1, N);
    {
        long long total = (long long)E * FDIM;
        int blocks = (int)((total + B - 1) / B);
        k_scatter<<<blocks, B>>>(rows, cols, E);
    }
    k_layer2<<<(N + 127) / 128, 128>>>(b1, W2, N);
    {
        long long total = (long long)E * FDIM;
        int blocks = (int)((total + B - 1) / B);
        k_scatter<<<blocks, B>>>(rows, cols, E);
    }
    k_zero_pool<<<(G * FDIM + B - 1) / B, B>>>(G);
    {
        long long total = (long long)N * FDIM;
        int blocks = (int)((total + B - 1) / B);
        k_pool<<<blocks, B>>>(batch, b2, N);
    }
    k_mlp<<<(G + B - 1) / B, B>>>(meta, Wh1, bh1, Wh2, bh2, out, G);
}

// round 3
// speedup vs baseline: 2.2863x; 2.2863x over previous
#include <cuda_runtime.h>
#include <cuda_bf16.h>

#define MAX_NODES 500000
#define MAX_GRAPHS 8192
#define FDIM 16

__device__ float g_deg[MAX_NODES];              // deg -> dinv in place
__device__ float g_h[MAX_NODES * FDIM];         // h * dinv  (prescaled)
__device__ float g_agg[MAX_NODES * FDIM];       // aggregation target
__device__ float g_pool[MAX_GRAPHS * FDIM];
__device__ float g_cnt[MAX_GRAPHS];

__device__ __forceinline__ void red_v4(float* addr, float4 v) {
    asm volatile("red.global.add.v4.f32 [%0], {%1,%2,%3,%4};"
                 :: "l"(addr), "f"(v.x), "f"(v.y), "f"(v.z), "f"(v.w)
                 : "memory");
}

// 1) deg init to 1 (self-loop)
__global__ void k_init_deg(int N) {
    int n = blockIdx.x * blockDim.x + threadIdx.x;
    if (n < N) g_deg[n] = 1.0f;
}

// 2) deg count over targets
__global__ void k_deg_count(const int* __restrict__ cols, int E) {
    int e = blockIdx.x * blockDim.x + threadIdx.x;
    if (e < E) atomicAdd(&g_deg[cols[e]], 1.0f);
}

// 3) dinv = rsqrt(deg)
__global__ void k_dinv(int N) {
    int n = blockIdx.x * blockDim.x + threadIdx.x;
    if (n < N) g_deg[n] = rsqrtf(g_deg[n]);
}

// 4) layer1: s = x@W1 ; g_h = s*dinv ; g_agg = s*dinv^2 (self-loop term)
//    x staged through smem for coalesced loads.
__global__ void k_layer1(const float* __restrict__ x, const float* __restrict__ W1,
                         int N) {
    __shared__ float sx[128 * 9];
    int base = blockIdx.x * 128;
    int n = base + threadIdx.x;
    // coalesced stage of this block's 128x9 slice
    int lim = min(128, N - base) * 9;
    for (int i = threadIdx.x; i < lim; i += 128)
        sx[i] = x[(long long)base * 9 + i];
    __syncthreads();
    if (n >= N) return;
    float xi[9];
#pragma unroll
    for (int k = 0; k < 9; k++) xi[k] = sx[threadIdx.x * 9 + k];
    float di = g_deg[n];
    float s[FDIM];
#pragma unroll
    for (int f = 0; f < FDIM; f++) {
        float acc = 0.0f;
#pragma unroll
        for (int k = 0; k < 9; k++) acc += xi[k] * __ldg(&W1[k * FDIM + f]);
        s[f] = acc;
    }
    float4* hp = (float4*)&g_h[n * FDIM];
    float4* ap = (float4*)&g_agg[n * FDIM];
#pragma unroll
    for (int q = 0; q < 4; q++) {
        float4 hv = make_float4(s[q*4+0]*di, s[q*4+1]*di, s[q*4+2]*di, s[q*4+3]*di);
        hp[q] = hv;
        ap[q] = make_float4(hv.x*di, hv.y*di, hv.z*di, hv.w*di);
    }
}

// 5) scatter: agg[c] += g_h[r] * dinv[c]   (g_h already has dinv[r] folded in)
//    4 threads/edge, float4 gather + red.global.v4 scatter.
__global__ void k_scatter(const int* __restrict__ rows,
                          const int* __restrict__ cols, int E) {
    long long idx = (long long)blockIdx.x * blockDim.x + threadIdx.x;
    int e = (int)(idx >> 2);
    int q = (int)(idx & 3);
    if (e >= E) return;
    int r = rows[e];
    int c = cols[e];
    float dc = g_deg[c];
    float4 hv = *(const float4*)&g_h[r * FDIM + q * 4];
    red_v4(&g_agg[c * FDIM + q * 4],
           make_float4(hv.x * dc, hv.y * dc, hv.z * dc, hv.w * dc));
}

// 6) finalize layer1 + layer2: a = relu(agg+b1); s = a@W2; g_h = s*dinv; g_agg = s*dinv^2
__global__ void k_layer2(const float* __restrict__ b1, const float* __restrict__ W2,
                         int N) {
    int n = blockIdx.x * blockDim.x + threadIdx.x;
    if (n >= N) return;
    float a[FDIM];
    const float4* ain = (const float4*)&g_agg[n * FDIM];
#pragma unroll
    for (int q = 0; q < 4; q++) {
        float4 v = ain[q];
        a[q*4+0] = fmaxf(v.x + __ldg(&b1[q*4+0]), 0.0f);
        a[q*4+1] = fmaxf(v.y + __ldg(&b1[q*4+1]), 0.0f);
        a[q*4+2] = fmaxf(v.z + __ldg(&b1[q*4+2]), 0.0f);
        a[q*4+3] = fmaxf(v.w + __ldg(&b1[q*4+3]), 0.0f);
    }
    float di = g_deg[n];
    float s[FDIM];
#pragma unroll
    for (int f = 0; f < FDIM; f++) {
        float acc = 0.0f;
#pragma unroll
        for (int k = 0; k < FDIM; k++) acc += a[k] * __ldg(&W2[k * FDIM + f]);
        s[f] = acc;
    }
    float4* hp = (float4*)&g_h[n * FDIM];
    float4* ap = (float4*)&g_agg[n * FDIM];
#pragma unroll
    for (int q = 0; q < 4; q++) {
        float4 hv = make_float4(s[q*4+0]*di, s[q*4+1]*di, s[q*4+2]*di, s[q*4+3]*di);
        hp[q] = hv;
        ap[q] = make_float4(hv.x*di, hv.y*di, hv.z*di, hv.w*di);
    }
}

// 7) zero pooling buffers
__global__ void k_zero_pool(int G) {
    int i = blockIdx.x * blockDim.x + threadIdx.x;
    if (i < G * FDIM) g_pool[i] = 0.0f;
    if (i < G) g_cnt[i] = 0.0f;
}

// 8) pool: relu(agg + b2) accumulated per graph; 4 threads/node, red.v4
__global__ void k_pool(const int* __restrict__ batch,
                       const float* __restrict__ b2, int N) {
    long long idx = (long long)blockIdx.x * blockDim.x + threadIdx.x;
    int n = (int)(idx >> 2);
    int q = (int)(idx & 3);
    if (n >= N) return;
    int g = batch[n];
    float4 v = *(const float4*)&g_agg[n * FDIM + q * 4];
    float4 r = make_float4(fmaxf(v.x + __ldg(&b2[q*4+0]), 0.0f),
                           fmaxf(v.y + __ldg(&b2[q*4+1]), 0.0f),
                           fmaxf(v.z + __ldg(&b2[q*4+2]), 0.0f),
                           fmaxf(v.w + __ldg(&b2[q*4+3]), 0.0f));
    red_v4(&g_pool[g * FDIM + q * 4], r);
    if (q == 0) atomicAdd(&g_cnt[g], 1.0f);
}

// 9) MLP head
__global__ void k_mlp(const float* __restrict__ meta,
                      const float* __restrict__ Wh1, const float* __restrict__ bh1,
                      const float* __restrict__ Wh2, const float* __restrict__ bh2,
                      float* __restrict__ out, int G) {
    int g = blockIdx.x * blockDim.x + threadIdx.x;
    if (g >= G) return;
    float inv = 1.0f / fmaxf(g_cnt[g], 1.0f);
    float z[FDIM];
#pragma unroll
    for (int f = 0; f < FDIM; f++) z[f] = __ldg(&bh1[f]);
#pragma unroll
    for (int k = 0; k < FDIM; k++) {
        float e = g_pool[g * FDIM + k] * inv;
#pragma unroll
        for (int f = 0; f < FDIM; f++) z[f] += e * __ldg(&Wh1[k * FDIM + f]);
    }
    for (int k = 0; k < 27; k++) {
        float m = meta[g * 27 + k];
#pragma unroll
        for (int f = 0; f < FDIM; f++) z[f] += m * __ldg(&Wh1[(FDIM + k) * FDIM + f]);
    }
    float o = __ldg(&bh2[0]);
#pragma unroll
    for (int f = 0; f < FDIM; f++) o += fmaxf(z[f], 0.0f) * __ldg(&Wh2[f]);
    out[g] = o;
}

extern "C" void kernel_launch(void* const* d_in, const int* in_sizes, int n_in,
                              void* d_out, int out_size) {
    const float* x    = (const float*)d_in[0];
    const int*   ei   = (const int*)d_in[1];
    const int*   batch= (const int*)d_in[2];
    const float* meta = (const float*)d_in[3];
    const float* W1   = (const float*)d_in[4];
    const float* b1   = (const float*)d_in[5];
    const float* W2   = (const float*)d_in[6];
    const float* b2   = (const float*)d_in[7];
    const float* Wh1  = (const float*)d_in[8];
    const float* bh1  = (const float*)d_in[9];
    const float* Wh2  = (const float*)d_in[10];
    const float* bh2  = (const float*)d_in[11];
    float* out = (float*)d_out;

    const int N = in_sizes[0] / 9;
    const int E = in_sizes[1] / 2;
    const int G = in_sizes[3] / 27;

    const int* rows = ei;      // source
    const int* cols = ei + E;  // target

    const int B = 256;
    k_init_deg<<<(N + B - 1) / B, B>>>(N);
    k_deg_count<<<(E + B - 1) / B, B>>>(cols, E);
    k_dinv<<<(N + B - 1) / B, B>>>(N);
    k_layer1<<<(N + 127) / 128, 128>>>(x, W1, N);
    {
        long long total = (long long)E * 4;
        k_scatter<<<(int)((total + B - 1) / B), B>>>(rows, cols, E);
    }
    k_layer2<<<(N + 127) / 128, 128>>>(b1, W2, N);
    {
        long long total = (long long)E * 4;
        k_scatter<<<(int)((total + B - 1) / B), B>>>(rows, cols, E);
    }
    k_zero_pool<<<(G * FDIM + B - 1) / B, B>>>(G);
    {
        long long total = (long long)N * 4;
        k_pool<<<(int)((total + B - 1) / B), B>>>(batch, b2, N);
    }
    k_mlp<<<(G + B - 1) / B, B>>>(meta, Wh1, bh1, Wh2, bh2, out, G);
}